// round 13
// baseline (speedup 1.0000x reference)
#include <cuda_runtime.h>
#include <math.h>

#define TT 100
#define BB 64
#define II 256
#define HH 512
#define H3 1536
#define H4 2048
#define NBLK 128          // persistent grid size (1 block/SM)

#define PF4(x) ((x) + ((x) >> 3))

// producer: release-add (no separate fence needed)
__device__ __forceinline__ void sig_add(unsigned* p) {
    asm volatile("red.release.gpu.global.add.u32 [%0], 1;" :: "l"(p) : "memory");
}

// ---------------- scratch (device globals) ----------------
__device__ float g_WihP[II * H4];                 // packed: [k][ (n%512)*4 + n/512 ]
__device__ float g_WhhP[HH * H4];
__device__ float g_biasP[H4];
__device__ float g_Gx[(size_t)TT * BB * H4];      // packed gate pre-activations from input path
__device__ float g_h[(size_t)(TT + 1) * BB * HH]; // h history [t][b][h]
__device__ float g_f[(size_t)TT * BB * HH];
__device__ float g_d[(size_t)TT * BB * H3];       // later overwritten with w = d * suffix-prod(f)
__device__ unsigned g_scnt[TT];                   // per-step completion counters

// ---------------- prep ----------------
__global__ void prep_kernel(const float* __restrict__ h0, const float* __restrict__ bih,
                            const float* __restrict__ bhh) {
    int i = blockIdx.x * blockDim.x + threadIdx.x;
    if (i < TT) g_scnt[i] = 0u;
    if (i < H4) g_biasP[(i & 511) * 4 + (i >> 9)] = bih[i] + bhh[i];
    if (i < BB * HH) g_h[i] = h0[i];
}

// ---------------- pack weights: in[2048][K] -> out[K][2048 packed] ----------------
__global__ void pack_w(const float* __restrict__ in, int K, int which) {
    __shared__ float s[32][33];
    int k0 = blockIdx.x * 32, n0 = blockIdx.y * 32;
    int tx = threadIdx.x, ty = threadIdx.y;
    for (int i = ty; i < 32; i += 8)
        s[i][tx] = in[(size_t)(n0 + i) * K + k0 + tx];
    __syncthreads();
    float* out = which ? g_WhhP : g_WihP;
    int g = n0 >> 9;
    int c = n0 & 511;
    for (int i = ty; i < 32; i += 8)
        out[(size_t)(k0 + i) * H4 + (c + tx) * 4 + g] = s[tx][i];
}

// ---------------- Gx = X[6400,256] @ WihP + biasP (packed out), acc[16][4] ----------------
__global__ void __launch_bounds__(256, 2) gx_kernel(const float* __restrict__ X) {
    __shared__ __align__(16) float As[8][132];
    __shared__ __align__(16) float Bs[8][140];
    const int tid = threadIdx.x;
    const int n0 = blockIdx.x * 128;
    const int m0 = blockIdx.y * 128;
    const int tj = (tid >> 5) * 16;
    const int tk = (tid & 31) * 4;
    const int pk = PF4(tid & 31);
    const int am = tid >> 1, ak = (tid & 1) * 4;
    const int bk = tid >> 5, bn_f4 = tid & 31;
    float acc[16][4] = {};
    for (int k0 = 0; k0 < II; k0 += 8) {
        float4 av = *(const float4*)(X + (size_t)(m0 + am) * II + k0 + ak);
        As[ak + 0][am] = av.x; As[ak + 1][am] = av.y; As[ak + 2][am] = av.z; As[ak + 3][am] = av.w;
        ((float4*)&Bs[bk][0])[PF4(bn_f4)] = *(const float4*)(g_WihP + (size_t)(k0 + bk) * H4 + n0 + bn_f4 * 4);
        __syncthreads();
#pragma unroll
        for (int u = 0; u < 8; u++) {
            float4 a0 = *(const float4*)&As[u][tj];
            float4 a1 = *(const float4*)&As[u][tj + 4];
            float4 a2 = *(const float4*)&As[u][tj + 8];
            float4 a3 = *(const float4*)&As[u][tj + 12];
            float4 bv = ((const float4*)&Bs[u][0])[pk];
            float aa[16] = {a0.x, a0.y, a0.z, a0.w, a1.x, a1.y, a1.z, a1.w,
                            a2.x, a2.y, a2.z, a2.w, a3.x, a3.y, a3.z, a3.w};
#pragma unroll
            for (int i = 0; i < 16; i++) {
                acc[i][0] += aa[i] * bv.x;
                acc[i][1] += aa[i] * bv.y;
                acc[i][2] += aa[i] * bv.z;
                acc[i][3] += aa[i] * bv.w;
            }
        }
        __syncthreads();
    }
    float4 bias4 = *(const float4*)(g_biasP + n0 + tk);
#pragma unroll
    for (int i = 0; i < 16; i++) {
        float* orow = g_Gx + (size_t)(m0 + tj + i) * H4 + n0 + tk;
        *(float4*)orow = make_float4(acc[i][0] + bias4.x, acc[i][1] + bias4.y,
                                     acc[i][2] + bias4.z, acc[i][3] + bias4.w);
    }
}

// ---------------- persistent recurrent loop: full-K, single barrier per step ----------------
// 128 blocks x 256 threads. Block bid owns packed cols [bid*16, +16) (= h-cols [bid*4, +4)),
// all 64 batches, full K=512. No split-K partial traffic; one global barrier per step.
// Thread GEMM id: kg (k-quarter 0..3) x mg (4-batch group 0..15) x cg (f4 col 0..3), acc[4][4].
// In-block k reduction via padded smem slab; cell = 1 thread per (batch, h-col).
#define AROW2 68          // Asm row stride (64 m + pad, 16B-aligned)
#define GROW 20           // Gred row stride (16 cols + pad, 16B-aligned)
__global__ void __launch_bounds__(256, 1)
loop_kernel(const float* __restrict__ c0, float* __restrict__ out_h, float* __restrict__ out_c) {
    extern __shared__ float sm[];
    float* Bsm  = sm;                       // [512][16]          32 KB
    float* Asm  = sm + 512 * 16;            // [2][64][AROW2]     ~34 KB
    float* Gred = Asm + 2 * 64 * AROW2;     // [4][64][GROW]      20 KB

    const int tid = threadIdx.x;
    const int bid = blockIdx.x;
    const int n0 = bid * 16;                // packed col base

    // ---- load this block's weight slab once: [512 k][16 cols] ----
#pragma unroll
    for (int r = 0; r < 8; r++) {
        int e = r * 256 + tid;              // 0..2047: k = e>>2, cf = e&3
        int k = e >> 2, cf = e & 3;
        *(float4*)(Bsm + k * 16 + cf * 4) =
            *(const float4*)(g_WhhP + (size_t)k * H4 + n0 + cf * 4);
    }

    // GEMM ids
    const int kg = tid >> 6;                // k-quarter of each 64-k chunk (16 k)
    const int mg = (tid & 63) >> 2;         // 0..15 (4 batches each)
    const int cg = tid & 3;                 // f4 col 0..3
    // A staging ids: thread loads 16 consecutive k for one m
    const int am = tid >> 2;                // 0..63 (batch row)
    const int aq = tid & 3;                 // k-16-group within chunk
    // cell ids
    const int cb = tid & 63;                // batch
    const int chc = tid >> 6;               // local h-col 0..3
    const int gcol = bid * 4 + chc;         // global h col
    float creg = c0[(size_t)cb * HH + gcol];

    __syncthreads();

    for (int t = 0; t < TT; t++) {
        // prefetch cell's Gx (const data, independent of h[t]) before the wait
        float4 gx4 = __ldcg((const float4*)(g_Gx + ((size_t)t * BB + cb) * H4 + 4 * gcol));

        // ---- wait for h[t] complete (skip t=0: prep wrote it) ----
        if (t > 0) {
            if (tid == 0) {
                volatile unsigned* p = &g_scnt[t - 1];
                while (*p < (unsigned)NBLK) __nanosleep(64);
                __threadfence();
            }
            __syncthreads();
        }

        const float* hsrc = g_h + (size_t)t * BB * HH;
        const float* hrow = hsrc + (size_t)am * HH + aq * 16;

        // ---- stage chunk 0 ----
        float4 pf0 = __ldcg((const float4*)(hrow + 0));
        float4 pf1 = __ldcg((const float4*)(hrow + 4));
        float4 pf2 = __ldcg((const float4*)(hrow + 8));
        float4 pf3 = __ldcg((const float4*)(hrow + 12));
        {
            float* Ab = Asm;                // buf 0
            int kb = aq * 16;
            Ab[(kb + 0) * AROW2 + am] = pf0.x; Ab[(kb + 1) * AROW2 + am] = pf0.y;
            Ab[(kb + 2) * AROW2 + am] = pf0.z; Ab[(kb + 3) * AROW2 + am] = pf0.w;
            Ab[(kb + 4) * AROW2 + am] = pf1.x; Ab[(kb + 5) * AROW2 + am] = pf1.y;
            Ab[(kb + 6) * AROW2 + am] = pf1.z; Ab[(kb + 7) * AROW2 + am] = pf1.w;
            Ab[(kb + 8) * AROW2 + am] = pf2.x; Ab[(kb + 9) * AROW2 + am] = pf2.y;
            Ab[(kb + 10) * AROW2 + am] = pf2.z; Ab[(kb + 11) * AROW2 + am] = pf2.w;
            Ab[(kb + 12) * AROW2 + am] = pf3.x; Ab[(kb + 13) * AROW2 + am] = pf3.y;
            Ab[(kb + 14) * AROW2 + am] = pf3.z; Ab[(kb + 15) * AROW2 + am] = pf3.w;
        }
        __syncthreads();

        float acc[4][4] = {};
        for (int c = 0; c < 8; c++) {
            if (c < 7) {
                const float* hn = hrow + (c + 1) * 64;
                pf0 = __ldcg((const float4*)(hn + 0));
                pf1 = __ldcg((const float4*)(hn + 4));
                pf2 = __ldcg((const float4*)(hn + 8));
                pf3 = __ldcg((const float4*)(hn + 12));
            }
            // compute this chunk: 16 k owned by kg
            {
                const float* Ab = Asm + (c & 1) * 64 * AROW2;
                const float* Bb = Bsm + (c * 64 + kg * 16) * 16;
#pragma unroll
                for (int uu = 0; uu < 16; uu++) {
                    float4 a = *(const float4*)(Ab + (kg * 16 + uu) * AROW2 + mg * 4);
                    float4 b = *(const float4*)(Bb + uu * 16 + cg * 4);
#pragma unroll
                    for (int i = 0; i < 4; i++) {
                        float av = (i == 0) ? a.x : (i == 1) ? a.y : (i == 2) ? a.z : a.w;
                        acc[i][0] += av * b.x;
                        acc[i][1] += av * b.y;
                        acc[i][2] += av * b.z;
                        acc[i][3] += av * b.w;
                    }
                }
            }
            if (c < 7) {
                __syncthreads();
                float* Ab = Asm + ((c + 1) & 1) * 64 * AROW2;
                int kb = aq * 16;
                Ab[(kb + 0) * AROW2 + am] = pf0.x; Ab[(kb + 1) * AROW2 + am] = pf0.y;
                Ab[(kb + 2) * AROW2 + am] = pf0.z; Ab[(kb + 3) * AROW2 + am] = pf0.w;
                Ab[(kb + 4) * AROW2 + am] = pf1.x; Ab[(kb + 5) * AROW2 + am] = pf1.y;
                Ab[(kb + 6) * AROW2 + am] = pf1.z; Ab[(kb + 7) * AROW2 + am] = pf1.w;
                Ab[(kb + 8) * AROW2 + am] = pf2.x; Ab[(kb + 9) * AROW2 + am] = pf2.y;
                Ab[(kb + 10) * AROW2 + am] = pf2.z; Ab[(kb + 11) * AROW2 + am] = pf2.w;
                Ab[(kb + 12) * AROW2 + am] = pf3.x; Ab[(kb + 13) * AROW2 + am] = pf3.y;
                Ab[(kb + 14) * AROW2 + am] = pf3.z; Ab[(kb + 15) * AROW2 + am] = pf3.w;
                __syncthreads();
            }
        }

        // ---- in-block k reduction: write acc to Gred[kg][m][col] ----
        __syncthreads();
#pragma unroll
        for (int i = 0; i < 4; i++) {
            *(float4*)(Gred + ((size_t)kg * 64 + mg * 4 + i) * GROW + cg * 4) =
                make_float4(acc[i][0], acc[i][1], acc[i][2], acc[i][3]);
        }
        __syncthreads();

        // ---- cell for (cb, gcol) ----
        {
            float4 g4 = gx4;
#pragma unroll
            for (int q = 0; q < 4; q++) {
                float4 p = *(const float4*)(Gred + ((size_t)q * 64 + cb) * GROW + chc * 4);
                g4.x += p.x; g4.y += p.y; g4.z += p.z; g4.w += p.w;
            }
            float i = 1.f / (1.f + expf(-g4.x));
            float f = 1.f / (1.f + expf(-g4.y));
            float g = tanhf(g4.z);
            float o = 1.f / (1.f + expf(-g4.w));
            float cx = creg;
            float cy = f * cx + i * g;
            float hy = o * tanhf(cy);
            creg = cy;
            size_t hb = (size_t)cb * HH + gcol;
            g_h[(size_t)(t + 1) * BB * HH + hb] = hy;
            out_h[(size_t)t * BB * HH + hb] = hy;
            g_f[(size_t)t * BB * HH + hb] = f;
            size_t db = (size_t)t * BB * H3 + (size_t)cb * H3 + gcol;
            g_d[db]          = g * i * (1.f - i);
            g_d[db + HH]     = cx * f * (1.f - f);
            g_d[db + 2 * HH] = i * (1.f - g) * (1.f + g);
            if (t == TT - 1) out_c[hb] = cy;
        }

        // ---- signal step complete ----
        __syncthreads();
        if (tid == 0) sig_add(&g_scnt[t]);
    }
}

// ---------------- reverse suffix-product scan ----------------
__global__ void scan_kernel(float* __restrict__ evb_out) {
    int idx = blockIdx.x * blockDim.x + threadIdx.x;  // < BB*H3
    int b = idx / H3, j = idx % H3;
    int h = j & (HH - 1);
    float p = 1.f, sum = 0.f;
    for (int t = TT - 1; t >= 0; t--) {
        size_t di = (size_t)t * BB * H3 + (size_t)b * H3 + j;
        float w = g_d[di] * p;
        g_d[di] = w;
        sum += w;
        p *= g_f[(size_t)t * BB * HH + (size_t)b * HH + h];
    }
    evb_out[idx] = sum;
}

// ---------------- batched ev GEMM: out[b][j][k] = sum_t w[t][b][j] * Xs[t][b][k] ----------------
__global__ void __launch_bounds__(256, 2)
ev_kernel(const float* __restrict__ Xs, int kdim, float* __restrict__ out) {
    __shared__ __align__(16) float Ws[8][132];
    __shared__ __align__(16) float Bs[8][140];
    if (Xs == nullptr) Xs = g_h;  // ev_hh: h_{t-1} history
    const int tid = threadIdx.x;
    const int b = blockIdx.z;
    const int j0 = blockIdx.y * 128;
    const int k0 = blockIdx.x * 128;
    const int tj = (tid >> 5) * 16;
    const int tk = (tid & 31) * 4;
    const int pk = PF4(tk >> 2);
    const int ltt = tid >> 5;
    const int lc = tid & 31;
    float acc[16][4] = {};
    for (int t0 = 0; t0 < TT; t0 += 8) {
        int t = t0 + ltt;
        float4 wv = make_float4(0.f, 0.f, 0.f, 0.f);
        float4 xv = make_float4(0.f, 0.f, 0.f, 0.f);
        if (t < TT) {
            wv = *(const float4*)(g_d + (size_t)t * BB * H3 + (size_t)b * H3 + j0 + lc * 4);
            xv = *(const float4*)(Xs + ((size_t)t * BB + b) * kdim + k0 + lc * 4);
        }
        *(float4*)&Ws[ltt][lc * 4] = wv;
        ((float4*)&Bs[ltt][0])[PF4(lc)] = xv;
        __syncthreads();
#pragma unroll
        for (int u = 0; u < 8; u++) {
            float4 a0 = *(const float4*)&Ws[u][tj];
            float4 a1 = *(const float4*)&Ws[u][tj + 4];
            float4 a2 = *(const float4*)&Ws[u][tj + 8];
            float4 a3 = *(const float4*)&Ws[u][tj + 12];
            float4 bv = ((const float4*)&Bs[u][0])[pk];
            float aa[16] = {a0.x, a0.y, a0.z, a0.w, a1.x, a1.y, a1.z, a1.w,
                            a2.x, a2.y, a2.z, a2.w, a3.x, a3.y, a3.z, a3.w};
#pragma unroll
            for (int i = 0; i < 16; i++) {
                acc[i][0] += aa[i] * bv.x;
                acc[i][1] += aa[i] * bv.y;
                acc[i][2] += aa[i] * bv.z;
                acc[i][3] += aa[i] * bv.w;
            }
        }
        __syncthreads();
    }
#pragma unroll
    for (int i = 0; i < 16; i++) {
        float* orow = out + ((size_t)b * H3 + j0 + tj + i) * kdim + k0 + tk;
        *(float4*)orow = make_float4(acc[i][0], acc[i][1], acc[i][2], acc[i][3]);
    }
}

// ---------------- launch ----------------
extern "C" void kernel_launch(void* const* d_in, const int* in_sizes, int n_in,
                              void* d_out, int out_size) {
    (void)in_sizes; (void)n_in; (void)out_size;
    const float* input = (const float*)d_in[0];
    const float* h0    = (const float*)d_in[1];
    const float* c0    = (const float*)d_in[2];
    const float* wih   = (const float*)d_in[3];
    const float* whh   = (const float*)d_in[4];
    const float* bih   = (const float*)d_in[5];
    const float* bhh   = (const float*)d_in[6];

    float* out         = (float*)d_out;
    float* out_outputs = out;
    float* out_cx      = out_outputs + (size_t)TT * BB * HH;
    float* out_evih    = out_cx + (size_t)BB * HH;
    float* out_evhh    = out_evih + (size_t)BB * H3 * II;
    float* out_evb     = out_evhh + (size_t)BB * H3 * HH;

    const int loop_smem = (512 * 16 + 2 * 64 * AROW2 + 4 * 64 * GROW) * 4;   // ~86 KB
    cudaFuncSetAttribute(loop_kernel, cudaFuncAttributeMaxDynamicSharedMemorySize, loop_smem);

    prep_kernel<<<512, 256>>>(h0, bih, bhh);
    pack_w<<<dim3(II / 32, H4 / 32), dim3(32, 8)>>>(wih, II, 0);
    pack_w<<<dim3(HH / 32, H4 / 32), dim3(32, 8)>>>(whh, HH, 1);
    gx_kernel<<<dim3(16, 50), 256>>>(input);

    loop_kernel<<<NBLK, 256, loop_smem>>>(c0, out_outputs, out_cx);

    scan_kernel<<<BB * H3 / 256, 256>>>(out_evb);
    ev_kernel<<<dim3(II / 128, H3 / 128, BB), 256>>>(input, II, out_evih);
    ev_kernel<<<dim3(HH / 128, H3 / 128, BB), 256>>>(nullptr, HH, out_evhh);
}

// round 15
// speedup vs baseline: 1.3789x; 1.3789x over previous
#include <cuda_runtime.h>
#include <math.h>

#define TT 100
#define BB 64
#define II 256
#define HH 512
#define H3 1536
#define H4 2048
#define NBLK 128          // persistent grid size (all co-resident)
#define KC 8              // K split chunks (512/64)
#define BKC 64            // K per chunk
#define BROW 284          // swizzled B row floats (71 f4 slots, PF4 max 70)
#define AROW 36           // A row floats (32 m + pad)

#define PF4(x) ((x) + ((x) >> 3))

// producer: release-add (no separate fence needed)
__device__ __forceinline__ void sig_add(unsigned* p) {
    asm volatile("red.release.gpu.global.add.u32 [%0], 1;" :: "l"(p) : "memory");
}

// ---------------- tf32 mma helpers ----------------
__device__ __forceinline__ unsigned f2tf32(float v) {
    unsigned r;
    asm("cvt.rna.tf32.f32 %0, %1;" : "=r"(r) : "f"(v));
    return r;
}
__device__ __forceinline__ void mma_tf32(float* d, unsigned a0, unsigned a1, unsigned a2, unsigned a3,
                                         unsigned b0, unsigned b1) {
    asm volatile("mma.sync.aligned.m16n8k8.row.col.f32.tf32.tf32.f32 "
                 "{%0,%1,%2,%3}, {%4,%5,%6,%7}, {%8,%9}, {%0,%1,%2,%3};"
                 : "+f"(d[0]), "+f"(d[1]), "+f"(d[2]), "+f"(d[3])
                 : "r"(a0), "r"(a1), "r"(a2), "r"(a3), "r"(b0), "r"(b1));
}

// ---------------- scratch (device globals) ----------------
__device__ float g_WihP[II * H4];                 // packed: [k][ (n%512)*4 + n/512 ]
__device__ float g_WhhP[HH * H4];
__device__ float g_biasP[H4];
__device__ float g_Gx[(size_t)TT * BB * H4];      // packed gate pre-activations from input path
__device__ float g_h[(size_t)(TT + 1) * BB * HH]; // h history [t][b][h]
__device__ float g_f[(size_t)TT * BB * HH];
__device__ float g_d[(size_t)TT * BB * H3];       // later overwritten with w = d * suffix-prod(f)
__device__ float g_gpart[16 * 32 * H4];           // split-K partials [kcmh][m-local][packed n]
__device__ unsigned g_cnt_g[TT][8];               // partials-done counters per (t, nt)
__device__ unsigned g_cnt_c[TT][8];               // cells-done counters per (t, nt)

// ---------------- prep ----------------
__global__ void prep_kernel(const float* __restrict__ h0, const float* __restrict__ bih,
                            const float* __restrict__ bhh) {
    int i = blockIdx.x * blockDim.x + threadIdx.x;
    if (i < TT * 8) { (&g_cnt_g[0][0])[i] = 0u; (&g_cnt_c[0][0])[i] = 0u; }
    if (i < H4) g_biasP[(i & 511) * 4 + (i >> 9)] = bih[i] + bhh[i];
    if (i < BB * HH) g_h[i] = h0[i];
}

// ---------------- pack weights: in[2048][K] -> out[K][2048 packed] ----------------
__global__ void pack_w(const float* __restrict__ in, int K, int which) {
    __shared__ float s[32][33];
    int k0 = blockIdx.x * 32, n0 = blockIdx.y * 32;
    int tx = threadIdx.x, ty = threadIdx.y;
    for (int i = ty; i < 32; i += 8)
        s[i][tx] = in[(size_t)(n0 + i) * K + k0 + tx];
    __syncthreads();
    float* out = which ? g_WhhP : g_WihP;
    int g = n0 >> 9;
    int c = n0 & 511;
    for (int i = ty; i < 32; i += 8)
        out[(size_t)(k0 + i) * H4 + (c + tx) * 4 + g] = s[tx][i];
}

// ---------------- Gx = X[6400,256] @ WihP + biasP (packed out), acc[16][4] ----------------
__global__ void __launch_bounds__(256, 2) gx_kernel(const float* __restrict__ X) {
    __shared__ __align__(16) float As[8][132];
    __shared__ __align__(16) float Bs[8][140];
    const int tid = threadIdx.x;
    const int n0 = blockIdx.x * 128;
    const int m0 = blockIdx.y * 128;
    const int tj = (tid >> 5) * 16;
    const int tk = (tid & 31) * 4;
    const int pk = PF4(tid & 31);
    const int am = tid >> 1, ak = (tid & 1) * 4;
    const int bk = tid >> 5, bn_f4 = tid & 31;
    float acc[16][4] = {};
    for (int k0 = 0; k0 < II; k0 += 8) {
        float4 av = *(const float4*)(X + (size_t)(m0 + am) * II + k0 + ak);
        As[ak + 0][am] = av.x; As[ak + 1][am] = av.y; As[ak + 2][am] = av.z; As[ak + 3][am] = av.w;
        ((float4*)&Bs[bk][0])[PF4(bn_f4)] = *(const float4*)(g_WihP + (size_t)(k0 + bk) * H4 + n0 + bn_f4 * 4);
        __syncthreads();
#pragma unroll
        for (int u = 0; u < 8; u++) {
            float4 a0 = *(const float4*)&As[u][tj];
            float4 a1 = *(const float4*)&As[u][tj + 4];
            float4 a2 = *(const float4*)&As[u][tj + 8];
            float4 a3 = *(const float4*)&As[u][tj + 12];
            float4 bv = ((const float4*)&Bs[u][0])[pk];
            float aa[16] = {a0.x, a0.y, a0.z, a0.w, a1.x, a1.y, a1.z, a1.w,
                            a2.x, a2.y, a2.z, a2.w, a3.x, a3.y, a3.z, a3.w};
#pragma unroll
            for (int i = 0; i < 16; i++) {
                acc[i][0] += aa[i] * bv.x;
                acc[i][1] += aa[i] * bv.y;
                acc[i][2] += aa[i] * bv.z;
                acc[i][3] += aa[i] * bv.w;
            }
        }
        __syncthreads();
    }
    float4 bias4 = *(const float4*)(g_biasP + n0 + tk);
#pragma unroll
    for (int i = 0; i < 16; i++) {
        float* orow = g_Gx + (size_t)(m0 + tj + i) * H4 + n0 + tk;
        *(float4*)orow = make_float4(acc[i][0] + bias4.x, acc[i][1] + bias4.y,
                                     acc[i][2] + bias4.z, acc[i][3] + bias4.w);
    }
}

// ---------------- persistent recurrent loop: R12-proven split-K (KC=8, M-split 2) ----------------
__global__ void __launch_bounds__(256, 1)
loop_kernel(const float* __restrict__ c0, float* __restrict__ out_h, float* __restrict__ out_c) {
    extern __shared__ float smdyn[];
    float* Bsm = smdyn;                  // [64][BROW]  (~72.7 KB)
    float* Asm = smdyn + 64 * BROW;      // [64][AROW]  (~9.2 KB)

    const int tid = threadIdx.x;
    const int nt = blockIdx.x & 7;
    const int kcmh = blockIdx.x >> 3;    // 0..15
    const int kc = kcmh >> 1;            // 0..7
    const int mh = kcmh & 1;             // 0..1
    const int n0 = nt * 256;
    const int k0 = kc * BKC;
    const int m0 = mh * 32;

    // stage weight chunk once (swizzled): 64k x 64 f4
    {
        const float* wsrc = g_WhhP + (size_t)k0 * H4 + n0;
#pragma unroll
        for (int r = 0; r < 16; r++) {
            int e = r * 256 + tid;
            int kk = e >> 6;
            int nf4 = e & 63;
            ((float4*)(Bsm + kk * BROW))[PF4(nf4)] = *(const float4*)(wsrc + (size_t)kk * H4 + nf4 * 4);
        }
    }

    const int tm = (tid >> 5) * 4;           // warp-uniform m (broadcast A reads), 0..28
    const int tn = (tid & 31) * 8;
    const int pn0 = PF4(tn >> 2);
    const int pn1 = PF4((tn >> 2) + 1);
    const int am = tid >> 3, ak = (tid & 7) * 8;   // A load map: 32 m rows x 8 k-octs

    // cell identity (fixed all steps)
    const int cb = kcmh * 4 + (tid >> 6);    // batch
    const int ch = nt * 64 + (tid & 63);     // global h col
    float creg = c0[(size_t)cb * HH + ch];

    for (int t = 0; t < TT; t++) {
        // ---- wait for h[t] producers (skip t=0: prep wrote it). nt_src = kc. ----
        if (t > 0) {
            if (tid == 0) {
                volatile unsigned* p = &g_cnt_c[t - 1][kc];
                while (*p < 16u) __nanosleep(64);
                __threadfence();
            }
            __syncthreads();
        }

        // ---- load A chunk: h[t][m0..m0+32)[k0..k0+64) -> Asm[k][m] ----
        const float* hsrc = g_h + (size_t)t * BB * HH;
        float4 v0 = __ldcg((const float4*)(hsrc + (size_t)(m0 + am) * HH + k0 + ak));
        float4 v1 = __ldcg((const float4*)(hsrc + (size_t)(m0 + am) * HH + k0 + ak + 4));
        Asm[(ak + 0) * AROW + am] = v0.x; Asm[(ak + 1) * AROW + am] = v0.y;
        Asm[(ak + 2) * AROW + am] = v0.z; Asm[(ak + 3) * AROW + am] = v0.w;
        Asm[(ak + 4) * AROW + am] = v1.x; Asm[(ak + 5) * AROW + am] = v1.y;
        Asm[(ak + 6) * AROW + am] = v1.z; Asm[(ak + 7) * AROW + am] = v1.w;

        // prefetch this step's Gx for the cell (independent of GEMM)
        float4 gx4 = __ldcg((const float4*)(g_Gx + ((size_t)t * BB + cb) * H4 + 4 * ch));
        __syncthreads();

        // ---- GEMM 32x256, K=64 ----
        float acc[4][8] = {};
#pragma unroll 16
        for (int u = 0; u < BKC; u++) {
            float4 a = *(const float4*)(Asm + u * AROW + tm);   // broadcast
            float4 b0 = ((const float4*)(Bsm + u * BROW))[pn0];
            float4 b1 = ((const float4*)(Bsm + u * BROW))[pn1];
            float aa[4] = {a.x, a.y, a.z, a.w};
            float bb[8] = {b0.x, b0.y, b0.z, b0.w, b1.x, b1.y, b1.z, b1.w};
#pragma unroll
            for (int i = 0; i < 4; i++)
#pragma unroll
                for (int j = 0; j < 8; j++)
                    acc[i][j] += aa[i] * bb[j];
        }
#pragma unroll
        for (int i = 0; i < 4; i++) {
            float* prow = g_gpart + ((size_t)kcmh * 32 + tm + i) * H4 + n0 + tn;
            *(float4*)prow = make_float4(acc[i][0], acc[i][1], acc[i][2], acc[i][3]);
            *(float4*)(prow + 4) = make_float4(acc[i][4], acc[i][5], acc[i][6], acc[i][7]);
        }

        // ---- signal partials done (release-add), wait for all 16 producers of our nt ----
        __syncthreads();
        if (tid == 0) {
            sig_add(&g_cnt_g[t][nt]);
            volatile unsigned* p = &g_cnt_g[t][nt];
            while (*p < 16u) __nanosleep(64);
            __threadfence();
        }
        __syncthreads();

        // ---- cell for (cb, ch): sum 8 partials (kc 0..7, mh = cb>>5) ----
        {
            float4 g4 = gx4;
#pragma unroll
            for (int q = 0; q < KC; q++) {
                int pk = q * 2 + (cb >> 5);
                float4 p = __ldcg((const float4*)(g_gpart + ((size_t)pk * 32 + (cb & 31)) * H4 + 4 * ch));
                g4.x += p.x; g4.y += p.y; g4.z += p.z; g4.w += p.w;
            }
            float i = 1.f / (1.f + expf(-g4.x));
            float f = 1.f / (1.f + expf(-g4.y));
            float g = tanhf(g4.z);
            float o = 1.f / (1.f + expf(-g4.w));
            float cx = creg;
            float cy = f * cx + i * g;
            float hy = o * tanhf(cy);
            creg = cy;
            size_t hb = (size_t)cb * HH + ch;
            g_h[(size_t)(t + 1) * BB * HH + hb] = hy;
            out_h[(size_t)t * BB * HH + hb] = hy;
            g_f[(size_t)t * BB * HH + hb] = f;
            size_t db = (size_t)t * BB * H3 + (size_t)cb * H3 + ch;
            g_d[db]          = g * i * (1.f - i);
            g_d[db + HH]     = cx * f * (1.f - f);
            g_d[db + 2 * HH] = i * (1.f - g) * (1.f + g);
            if (t == TT - 1) out_c[hb] = cy;
        }

        // ---- signal cells done (release-add) ----
        __syncthreads();
        if (tid == 0) sig_add(&g_cnt_c[t][nt]);
    }
}

// ---------------- reverse suffix-product scan ----------------
__global__ void scan_kernel(float* __restrict__ evb_out) {
    int idx = blockIdx.x * blockDim.x + threadIdx.x;  // < BB*H3
    int b = idx / H3, j = idx % H3;
    int h = j & (HH - 1);
    float p = 1.f, sum = 0.f;
    for (int t = TT - 1; t >= 0; t--) {
        size_t di = (size_t)t * BB * H3 + (size_t)b * H3 + j;
        float w = g_d[di] * p;
        g_d[di] = w;
        sum += w;
        p *= g_f[(size_t)t * BB * HH + (size_t)b * HH + h];
    }
    evb_out[idx] = sum;
}

// ---------------- batched ev GEMM via tf32 mma: out[b][j][k] = sum_t w[t][b][j] * x[t][b][k] ----------------
// Block tile: 128 j x 128 k per batch; 8 warps = 4 j-groups(32) x 2 k-groups(64).
// Warp: 2 m16-tiles x 8 n8-tiles, K(reduction)=104 (zero-padded past T=100).
// Fragments loaded directly from global (A/B tiles are L1-resident); fp32 accumulate.
__global__ void __launch_bounds__(256, 2)
ev_mma_kernel(const float* __restrict__ Xs, int kdim, float* __restrict__ out) {
    if (Xs == nullptr) Xs = g_h;  // ev_hh: h_{t-1} history = g_h[t] slice
    const int b = blockIdx.z;
    const int j0 = blockIdx.y * 128;
    const int k0 = blockIdx.x * 128;
    const int w = threadIdx.x >> 5, lane = threadIdx.x & 31;
    const int gr = lane >> 2;            // 0..7
    const int cg = lane & 3;             // 0..3
    const int jbase = j0 + (w & 3) * 32;
    const int kbase = k0 + (w >> 2) * 64;

    const float* __restrict__ Wp = g_d + (size_t)b * H3;       // + t*BB*H3 + j
    const float* __restrict__ Xp = Xs + (size_t)b * kdim;      // + t*BB*kdim + k
    const size_t wstride = (size_t)BB * H3;
    const size_t xstride = (size_t)BB * kdim;

    float acc[2][8][4];
#pragma unroll
    for (int mi = 0; mi < 2; mi++)
#pragma unroll
        for (int ni = 0; ni < 8; ni++)
#pragma unroll
            for (int q = 0; q < 4; q++) acc[mi][ni][q] = 0.f;

    for (int ks = 0; ks < 13; ks++) {
        const int tA = ks * 8 + cg;          // always < 100 (max 99)
        const int tA2 = tA + 4;              // >= 100 only at ks == 12
        const bool ok2 = (tA2 < TT);
        const float* __restrict__ wr0 = Wp + (size_t)tA * wstride;
        const float* __restrict__ wr1 = Wp + (size_t)(ok2 ? tA2 : 0) * wstride;
        const float* __restrict__ xr0 = Xp + (size_t)tA * xstride;
        const float* __restrict__ xr1 = Xp + (size_t)(ok2 ? tA2 : 0) * xstride;

        // A fragments: a0=A[gr][c], a1=A[gr+8][c], a2=A[gr][c+4], a3=A[gr+8][c+4]  (row=j, col=t)
        unsigned afr[2][4];
#pragma unroll
        for (int mi = 0; mi < 2; mi++) {
            int jr = jbase + mi * 16 + gr;
            afr[mi][0] = f2tf32(wr0[jr]);
            afr[mi][1] = f2tf32(wr0[jr + 8]);
            afr[mi][2] = f2tf32(ok2 ? wr1[jr] : 0.f);
            afr[mi][3] = f2tf32(ok2 ? wr1[jr + 8] : 0.f);
        }
        // B fragments per n-tile: b0=B[c][col]=x[tA][kc], b1=x[tA+4][kc]  (row=t, col=k)
#pragma unroll
        for (int ni = 0; ni < 8; ni++) {
            int kc = kbase + ni * 8 + gr;
            unsigned b0 = f2tf32(xr0[kc]);
            unsigned b1 = f2tf32(ok2 ? xr1[kc] : 0.f);
            mma_tf32(acc[0][ni], afr[0][0], afr[0][1], afr[0][2], afr[0][3], b0, b1);
            mma_tf32(acc[1][ni], afr[1][0], afr[1][1], afr[1][2], afr[1][3], b0, b1);
        }
    }

    // store: d0=D[gr][2c], d1=D[gr][2c+1], d2=D[gr+8][2c], d3=D[gr+8][2c+1]
#pragma unroll
    for (int mi = 0; mi < 2; mi++) {
        int jr = jbase + mi * 16 + gr;
#pragma unroll
        for (int ni = 0; ni < 8; ni++) {
            int col = kbase + ni * 8 + 2 * cg;
            float* o0 = out + ((size_t)b * H3 + jr) * kdim + col;
            float* o1 = out + ((size_t)b * H3 + jr + 8) * kdim + col;
            *(float2*)o0 = make_float2(acc[mi][ni][0], acc[mi][ni][1]);
            *(float2*)o1 = make_float2(acc[mi][ni][2], acc[mi][ni][3]);
        }
    }
}

// ---------------- launch ----------------
extern "C" void kernel_launch(void* const* d_in, const int* in_sizes, int n_in,
                              void* d_out, int out_size) {
    (void)in_sizes; (void)n_in; (void)out_size;
    const float* input = (const float*)d_in[0];
    const float* h0    = (const float*)d_in[1];
    const float* c0    = (const float*)d_in[2];
    const float* wih   = (const float*)d_in[3];
    const float* whh   = (const float*)d_in[4];
    const float* bih   = (const float*)d_in[5];
    const float* bhh   = (const float*)d_in[6];

    float* out         = (float*)d_out;
    float* out_outputs = out;
    float* out_cx      = out_outputs + (size_t)TT * BB * HH;
    float* out_evih    = out_cx + (size_t)BB * HH;
    float* out_evhh    = out_evih + (size_t)BB * H3 * II;
    float* out_evb     = out_evhh + (size_t)BB * H3 * HH;

    const int loop_smem = (64 * BROW + 64 * AROW) * 4;   // ~82 KB
    cudaFuncSetAttribute(loop_kernel, cudaFuncAttributeMaxDynamicSharedMemorySize, loop_smem);

    prep_kernel<<<512, 256>>>(h0, bih, bhh);
    pack_w<<<dim3(II / 32, H4 / 32), dim3(32, 8)>>>(wih, II, 0);
    pack_w<<<dim3(HH / 32, H4 / 32), dim3(32, 8)>>>(whh, HH, 1);
    gx_kernel<<<dim3(16, 50), 256>>>(input);

    loop_kernel<<<NBLK, 256, loop_smem>>>(c0, out_outputs, out_cx);

    scan_kernel<<<BB * H3 / 256, 256>>>(out_evb);
    ev_mma_kernel<<<dim3(II / 128, H3 / 128, BB), 256>>>(input, II, out_evih);
    ev_mma_kernel<<<dim3(HH / 128, H3 / 128, BB), 256>>>(nullptr, HH, out_evhh);
}

// round 16
// speedup vs baseline: 1.5596x; 1.1310x over previous
#include <cuda_runtime.h>
#include <math.h>

#define TT 100
#define BB 64
#define II 256
#define HH 512
#define H3 1536
#define H4 2048
#define NBLK 128          // persistent grid size (all co-resident)
#define KC 8              // K split chunks (512/64)
#define BKC 64            // K per chunk
#define AROW 40           // Asm row stride: fragment reads bank = 8cg+gr (conflict-free)
#define WROW 68           // Whi/Wlo row stride: b-reads bank = 4gr+cg (conflict-free)

#define PF4(x) ((x) + ((x) >> 3))

// producer: release-add (no separate fence needed)
__device__ __forceinline__ void sig_add(unsigned* p) {
    asm volatile("red.release.gpu.global.add.u32 [%0], 1;" :: "l"(p) : "memory");
}

// ---------------- tf32 mma helpers (layouts validated in R15) ----------------
__device__ __forceinline__ unsigned f2tf32(float v) {
    unsigned r;
    asm("cvt.rna.tf32.f32 %0, %1;" : "=r"(r) : "f"(v));
    return r;
}
__device__ __forceinline__ void mma_tf32(float* d, const unsigned* a, unsigned b0, unsigned b1) {
    asm volatile("mma.sync.aligned.m16n8k8.row.col.f32.tf32.tf32.f32 "
                 "{%0,%1,%2,%3}, {%4,%5,%6,%7}, {%8,%9}, {%0,%1,%2,%3};"
                 : "+f"(d[0]), "+f"(d[1]), "+f"(d[2]), "+f"(d[3])
                 : "r"(a[0]), "r"(a[1]), "r"(a[2]), "r"(a[3]), "r"(b0), "r"(b1));
}

// ---------------- scratch (device globals) ----------------
__device__ float g_WihP[II * H4];                 // packed: [k][ (n%512)*4 + n/512 ]
__device__ float g_WhhP[HH * H4];
__device__ float g_biasP[H4];
__device__ float g_Gx[(size_t)TT * BB * H4];      // packed gate pre-activations from input path
__device__ float g_h[(size_t)(TT + 1) * BB * HH]; // h history [t][b][h]
__device__ float g_f[(size_t)TT * BB * HH];
__device__ float g_d[(size_t)TT * BB * H3];       // later overwritten with w = d * suffix-prod(f)
__device__ float g_gpart[16 * 32 * H4];           // split-K partials [kcmh][m-local][packed n]
__device__ unsigned g_cnt_g[TT][8];               // partials-done counters per (t, nt)
__device__ unsigned g_cnt_c[TT][8];               // cells-done counters per (t, nt)

// ---------------- prep ----------------
__global__ void prep_kernel(const float* __restrict__ h0, const float* __restrict__ bih,
                            const float* __restrict__ bhh) {
    int i = blockIdx.x * blockDim.x + threadIdx.x;
    if (i < TT * 8) { (&g_cnt_g[0][0])[i] = 0u; (&g_cnt_c[0][0])[i] = 0u; }
    if (i < H4) g_biasP[(i & 511) * 4 + (i >> 9)] = bih[i] + bhh[i];
    if (i < BB * HH) g_h[i] = h0[i];
}

// ---------------- pack weights: in[2048][K] -> out[K][2048 packed] ----------------
__global__ void pack_w(const float* __restrict__ in, int K, int which) {
    __shared__ float s[32][33];
    int k0 = blockIdx.x * 32, n0 = blockIdx.y * 32;
    int tx = threadIdx.x, ty = threadIdx.y;
    for (int i = ty; i < 32; i += 8)
        s[i][tx] = in[(size_t)(n0 + i) * K + k0 + tx];
    __syncthreads();
    float* out = which ? g_WhhP : g_WihP;
    int g = n0 >> 9;
    int c = n0 & 511;
    for (int i = ty; i < 32; i += 8)
        out[(size_t)(k0 + i) * H4 + (c + tx) * 4 + g] = s[tx][i];
}

// ---------------- Gx = X[6400,256] @ WihP + biasP (packed out), acc[16][4] scalar ----------------
__global__ void __launch_bounds__(256, 2) gx_kernel(const float* __restrict__ X) {
    __shared__ __align__(16) float As[8][132];
    __shared__ __align__(16) float Bs[8][140];
    const int tid = threadIdx.x;
    const int n0 = blockIdx.x * 128;
    const int m0 = blockIdx.y * 128;
    const int tj = (tid >> 5) * 16;
    const int tk = (tid & 31) * 4;
    const int pk = PF4(tid & 31);
    const int am = tid >> 1, ak = (tid & 1) * 4;
    const int bk = tid >> 5, bn_f4 = tid & 31;
    float acc[16][4] = {};
    for (int k0 = 0; k0 < II; k0 += 8) {
        float4 av = *(const float4*)(X + (size_t)(m0 + am) * II + k0 + ak);
        As[ak + 0][am] = av.x; As[ak + 1][am] = av.y; As[ak + 2][am] = av.z; As[ak + 3][am] = av.w;
        ((float4*)&Bs[bk][0])[PF4(bn_f4)] = *(const float4*)(g_WihP + (size_t)(k0 + bk) * H4 + n0 + bn_f4 * 4);
        __syncthreads();
#pragma unroll
        for (int u = 0; u < 8; u++) {
            float4 a0 = *(const float4*)&As[u][tj];
            float4 a1 = *(const float4*)&As[u][tj + 4];
            float4 a2 = *(const float4*)&As[u][tj + 8];
            float4 a3 = *(const float4*)&As[u][tj + 12];
            float4 bv = ((const float4*)&Bs[u][0])[pk];
            float aa[16] = {a0.x, a0.y, a0.z, a0.w, a1.x, a1.y, a1.z, a1.w,
                            a2.x, a2.y, a2.z, a2.w, a3.x, a3.y, a3.z, a3.w};
#pragma unroll
            for (int i = 0; i < 16; i++) {
                acc[i][0] += aa[i] * bv.x;
                acc[i][1] += aa[i] * bv.y;
                acc[i][2] += aa[i] * bv.z;
                acc[i][3] += aa[i] * bv.w;
            }
        }
        __syncthreads();
    }
    float4 bias4 = *(const float4*)(g_biasP + n0 + tk);
#pragma unroll
    for (int i = 0; i < 16; i++) {
        float* orow = g_Gx + (size_t)(m0 + tj + i) * H4 + n0 + tk;
        *(float4*)orow = make_float4(acc[i][0] + bias4.x, acc[i][1] + bias4.y,
                                     acc[i][2] + bias4.z, acc[i][3] + bias4.w);
    }
}

// ---------------- persistent recurrent loop: R12 skeleton + tf32 hi/lo mma GEMM ----------------
// Block (nt, kcmh): GEMM tile M=32, N=256 packed, K=64. 8 warps, each owns N-slice w*32.
// acc = Ahi*Bhi + Ahi*Blo + Alo*Bhi (error ~2^-22, fp32-grade for the recurrence).
__global__ void __launch_bounds__(256, 1)
loop_kernel(const float* __restrict__ c0, float* __restrict__ out_h, float* __restrict__ out_c) {
    extern __shared__ float sm[];
    float* Whi = sm;                    // [256 n][WROW]  (~69.6 KB)
    float* Wlo = sm + 256 * WROW;       // [256 n][WROW]  (~69.6 KB)
    float* Asm = Wlo + 256 * WROW;      // [64 k][AROW]   (10.2 KB)

    const int tid = threadIdx.x;
    const int nt = blockIdx.x & 7;
    const int kcmh = blockIdx.x >> 3;    // 0..15
    const int kc = kcmh >> 1;            // 0..7
    const int mh = kcmh & 1;             // 0..1
    const int n0 = nt * 256;
    const int k0 = kc * BKC;
    const int m0 = mh * 32;

    // ---- stage hi/lo weights once: [n local][k local] ----
    {
        const float* wsrc = g_WhhP + (size_t)k0 * H4 + n0;
#pragma unroll
        for (int r = 0; r < 16; r++) {
            int e = r * 256 + tid;
            int kk = e >> 6;            // k local 0..63
            int nf4 = e & 63;           // n f4 0..63
            float4 wv = *(const float4*)(wsrc + (size_t)kk * H4 + nf4 * 4);
            float wq[4] = {wv.x, wv.y, wv.z, wv.w};
#pragma unroll
            for (int q = 0; q < 4; q++) {
                float hf = __uint_as_float(f2tf32(wq[q]));
                float lf = __uint_as_float(f2tf32(wq[q] - hf));
                Whi[(size_t)(nf4 * 4 + q) * WROW + kk] = hf;
                Wlo[(size_t)(nf4 * 4 + q) * WROW + kk] = lf;
            }
        }
    }

    const int w = tid >> 5, lane = tid & 31;
    const int gr = lane >> 2;            // 0..7
    const int cg = lane & 3;             // 0..3
    const int nb = w * 32;               // warp n-slice within 256
    const int am = tid >> 3, ak = (tid & 7) * 8;   // A staging map (R12-proven)

    // cell identity (fixed all steps)
    const int cb = kcmh * 4 + (tid >> 6);    // batch
    const int ch = nt * 64 + (tid & 63);     // global h col
    float creg = c0[(size_t)cb * HH + ch];

    for (int t = 0; t < TT; t++) {
        // ---- wait for h[t] producers (skip t=0: prep wrote it). nt_src = kc. ----
        if (t > 0) {
            if (tid == 0) {
                volatile unsigned* p = &g_cnt_c[t - 1][kc];
                while (*p < 16u) __nanosleep(64);
                __threadfence();
            }
            __syncthreads();
        }

        // ---- stage A: h[t][m0..m0+32)[k0..k0+64) -> Asm[k][m] ----
        const float* hsrc = g_h + (size_t)t * BB * HH;
        float4 v0 = __ldcg((const float4*)(hsrc + (size_t)(m0 + am) * HH + k0 + ak));
        float4 v1 = __ldcg((const float4*)(hsrc + (size_t)(m0 + am) * HH + k0 + ak + 4));
        Asm[(ak + 0) * AROW + am] = v0.x; Asm[(ak + 1) * AROW + am] = v0.y;
        Asm[(ak + 2) * AROW + am] = v0.z; Asm[(ak + 3) * AROW + am] = v0.w;
        Asm[(ak + 4) * AROW + am] = v1.x; Asm[(ak + 5) * AROW + am] = v1.y;
        Asm[(ak + 6) * AROW + am] = v1.z; Asm[(ak + 7) * AROW + am] = v1.w;

        // prefetch this step's Gx for the cell (independent of GEMM)
        float4 gx4 = __ldcg((const float4*)(g_Gx + ((size_t)t * BB + cb) * H4 + 4 * ch));
        __syncthreads();

        // ---- GEMM 32x256, K=64 via tf32 mma hi/lo ----
        float acc[2][4][4];
#pragma unroll
        for (int mi = 0; mi < 2; mi++)
#pragma unroll
            for (int ni = 0; ni < 4; ni++)
#pragma unroll
                for (int q = 0; q < 4; q++) acc[mi][ni][q] = 0.f;

#pragma unroll
        for (int ks = 0; ks < 8; ks++) {
            // A fragments hi/lo: a0=A[gr][c], a1=A[gr+8][c], a2=A[gr][c+4], a3=A[gr+8][c+4]
            unsigned ahi[2][4], alo[2][4];
#pragma unroll
            for (int mi = 0; mi < 2; mi++) {
                int mb = mi * 16 + gr;
                float e0 = Asm[(ks * 8 + cg) * AROW + mb];
                float e1 = Asm[(ks * 8 + cg) * AROW + mb + 8];
                float e2 = Asm[(ks * 8 + cg + 4) * AROW + mb];
                float e3 = Asm[(ks * 8 + cg + 4) * AROW + mb + 8];
                ahi[mi][0] = f2tf32(e0); alo[mi][0] = f2tf32(e0 - __uint_as_float(ahi[mi][0]));
                ahi[mi][1] = f2tf32(e1); alo[mi][1] = f2tf32(e1 - __uint_as_float(ahi[mi][1]));
                ahi[mi][2] = f2tf32(e2); alo[mi][2] = f2tf32(e2 - __uint_as_float(ahi[mi][2]));
                ahi[mi][3] = f2tf32(e3); alo[mi][3] = f2tf32(e3 - __uint_as_float(ahi[mi][3]));
            }
#pragma unroll
            for (int ni = 0; ni < 4; ni++) {
                int n = nb + ni * 8 + gr;
                unsigned bhi0 = __float_as_uint(Whi[(size_t)n * WROW + ks * 8 + cg]);
                unsigned bhi1 = __float_as_uint(Whi[(size_t)n * WROW + ks * 8 + cg + 4]);
                unsigned blo0 = __float_as_uint(Wlo[(size_t)n * WROW + ks * 8 + cg]);
                unsigned blo1 = __float_as_uint(Wlo[(size_t)n * WROW + ks * 8 + cg + 4]);
#pragma unroll
                for (int mi = 0; mi < 2; mi++) {
                    mma_tf32(acc[mi][ni], ahi[mi], bhi0, bhi1);
                    mma_tf32(acc[mi][ni], ahi[mi], blo0, blo1);
                    mma_tf32(acc[mi][ni], alo[mi], bhi0, bhi1);
                }
            }
        }

        // ---- write partials: D[m][n] rows gr / gr+8 per mtile ----
#pragma unroll
        for (int mi = 0; mi < 2; mi++) {
            int mrow = mi * 16 + gr;
#pragma unroll
            for (int ni = 0; ni < 4; ni++) {
                int col = n0 + nb + ni * 8 + 2 * cg;
                float* p0 = g_gpart + ((size_t)kcmh * 32 + mrow) * H4 + col;
                float* p1 = g_gpart + ((size_t)kcmh * 32 + mrow + 8) * H4 + col;
                *(float2*)p0 = make_float2(acc[mi][ni][0], acc[mi][ni][1]);
                *(float2*)p1 = make_float2(acc[mi][ni][2], acc[mi][ni][3]);
            }
        }

        // ---- signal partials done (release-add), wait for all 16 producers of our nt ----
        __syncthreads();                      // Asm also reused next step
        if (tid == 0) {
            sig_add(&g_cnt_g[t][nt]);
            volatile unsigned* p = &g_cnt_g[t][nt];
            while (*p < 16u) __nanosleep(64);
            __threadfence();
        }
        __syncthreads();

        // ---- cell for (cb, ch): sum 8 partials (kc 0..7, mh = cb>>5) ----
        {
            float4 g4 = gx4;
#pragma unroll
            for (int q = 0; q < KC; q++) {
                int pk = q * 2 + (cb >> 5);
                float4 p = __ldcg((const float4*)(g_gpart + ((size_t)pk * 32 + (cb & 31)) * H4 + 4 * ch));
                g4.x += p.x; g4.y += p.y; g4.z += p.z; g4.w += p.w;
            }
            float i = 1.f / (1.f + expf(-g4.x));
            float f = 1.f / (1.f + expf(-g4.y));
            float g = tanhf(g4.z);
            float o = 1.f / (1.f + expf(-g4.w));
            float cx = creg;
            float cy = f * cx + i * g;
            float hy = o * tanhf(cy);
            creg = cy;
            size_t hb = (size_t)cb * HH + ch;
            g_h[(size_t)(t + 1) * BB * HH + hb] = hy;
            out_h[(size_t)t * BB * HH + hb] = hy;
            g_f[(size_t)t * BB * HH + hb] = f;
            size_t db = (size_t)t * BB * H3 + (size_t)cb * H3 + ch;
            g_d[db]          = g * i * (1.f - i);
            g_d[db + HH]     = cx * f * (1.f - f);
            g_d[db + 2 * HH] = i * (1.f - g) * (1.f + g);
            if (t == TT - 1) out_c[hb] = cy;
        }

        // ---- signal cells done (release-add) ----
        __syncthreads();
        if (tid == 0) sig_add(&g_cnt_c[t][nt]);
    }
}

// ---------------- reverse suffix-product scan ----------------
__global__ void scan_kernel(float* __restrict__ evb_out) {
    int idx = blockIdx.x * blockDim.x + threadIdx.x;  // < BB*H3
    int b = idx / H3, j = idx % H3;
    int h = j & (HH - 1);
    float p = 1.f, sum = 0.f;
    for (int t = TT - 1; t >= 0; t--) {
        size_t di = (size_t)t * BB * H3 + (size_t)b * H3 + j;
        float w = g_d[di] * p;
        g_d[di] = w;
        sum += w;
        p *= g_f[(size_t)t * BB * HH + (size_t)b * HH + h];
    }
    evb_out[idx] = sum;
}

// ---------------- batched ev GEMM via tf32 mma, smem-staged fragments ----------------
// Block tile: 128 j x 128 k per batch; 8 warps = 4 j-groups(32) x 2 k-groups(64).
// Stage 8 t-slices per iter (coalesced f4), fragments from conflict-free LDS (row pad 136).
__global__ void __launch_bounds__(256, 2)
ev_mma_kernel(const float* __restrict__ Xs, int kdim, float* __restrict__ out) {
    __shared__ __align__(16) float Ws[8][136];
    __shared__ __align__(16) float Xsm[8][136];
    if (Xs == nullptr) Xs = g_h;  // ev_hh: h_{t-1} history = g_h[t] slice
    const int tid = threadIdx.x;
    const int b = blockIdx.z;
    const int j0 = blockIdx.y * 128;
    const int k0 = blockIdx.x * 128;
    const int w = tid >> 5, lane = tid & 31;
    const int gr = lane >> 2;            // 0..7
    const int cg = lane & 3;             // 0..3
    const int jbase = (w & 3) * 32;
    const int kbase = (w >> 2) * 64;
    const int lc = lane;                 // staging f4 col (0..31)

    float acc[2][8][4];
#pragma unroll
    for (int mi = 0; mi < 2; mi++)
#pragma unroll
        for (int ni = 0; ni < 8; ni++)
#pragma unroll
            for (int q = 0; q < 4; q++) acc[mi][ni][q] = 0.f;

    for (int ks = 0; ks < 13; ks++) {
        int t = ks * 8 + w;              // staging slice: warp w loads t-slice
        float4 wv = make_float4(0.f, 0.f, 0.f, 0.f);
        float4 xv = make_float4(0.f, 0.f, 0.f, 0.f);
        if (t < TT) {
            wv = *(const float4*)(g_d + (size_t)t * BB * H3 + (size_t)b * H3 + j0 + lc * 4);
            xv = *(const float4*)(Xs + ((size_t)t * BB + b) * kdim + k0 + lc * 4);
        }
        __syncthreads();
        *(float4*)&Ws[w][lc * 4] = wv;
        *(float4*)&Xsm[w][lc * 4] = xv;
        __syncthreads();

        // A fragments: a0=W[j=gr][t=cg], a1=W[gr+8][cg], a2=W[gr][cg+4], a3=W[gr+8][cg+4]
        unsigned afr[2][4];
#pragma unroll
        for (int mi = 0; mi < 2; mi++) {
            int jr = jbase + mi * 16 + gr;
            afr[mi][0] = f2tf32(Ws[cg][jr]);
            afr[mi][1] = f2tf32(Ws[cg][jr + 8]);
            afr[mi][2] = f2tf32(Ws[cg + 4][jr]);
            afr[mi][3] = f2tf32(Ws[cg + 4][jr + 8]);
        }
#pragma unroll
        for (int ni = 0; ni < 8; ni++) {
            int kc = kbase + ni * 8 + gr;
            unsigned b0 = f2tf32(Xsm[cg][kc]);
            unsigned b1 = f2tf32(Xsm[cg + 4][kc]);
            mma_tf32(acc[0][ni], afr[0], b0, b1);
            mma_tf32(acc[1][ni], afr[1], b0, b1);
        }
    }

    // store: d0=D[gr][2c], d1=D[gr][2c+1], d2=D[gr+8][2c], d3=D[gr+8][2c+1]
#pragma unroll
    for (int mi = 0; mi < 2; mi++) {
        int jr = j0 + jbase + mi * 16 + gr;
#pragma unroll
        for (int ni = 0; ni < 8; ni++) {
            int col = k0 + kbase + ni * 8 + 2 * cg;
            float* o0 = out + ((size_t)b * H3 + jr) * kdim + col;
            float* o1 = out + ((size_t)b * H3 + jr + 8) * kdim + col;
            *(float2*)o0 = make_float2(acc[mi][ni][0], acc[mi][ni][1]);
            *(float2*)o1 = make_float2(acc[mi][ni][2], acc[mi][ni][3]);
        }
    }
}

// ---------------- launch ----------------
extern "C" void kernel_launch(void* const* d_in, const int* in_sizes, int n_in,
                              void* d_out, int out_size) {
    (void)in_sizes; (void)n_in; (void)out_size;
    const float* input = (const float*)d_in[0];
    const float* h0    = (const float*)d_in[1];
    const float* c0    = (const float*)d_in[2];
    const float* wih   = (const float*)d_in[3];
    const float* whh   = (const float*)d_in[4];
    const float* bih   = (const float*)d_in[5];
    const float* bhh   = (const float*)d_in[6];

    float* out         = (float*)d_out;
    float* out_outputs = out;
    float* out_cx      = out_outputs + (size_t)TT * BB * HH;
    float* out_evih    = out_cx + (size_t)BB * HH;
    float* out_evhh    = out_evih + (size_t)BB * H3 * II;
    float* out_evb     = out_evhh + (size_t)BB * H3 * HH;

    const int loop_smem = (2 * 256 * WROW + 64 * AROW) * 4;   // ~146 KB
    cudaFuncSetAttribute(loop_kernel, cudaFuncAttributeMaxDynamicSharedMemorySize, loop_smem);

    prep_kernel<<<512, 256>>>(h0, bih, bhh);
    pack_w<<<dim3(II / 32, H4 / 32), dim3(32, 8)>>>(wih, II, 0);
    pack_w<<<dim3(HH / 32, H4 / 32), dim3(32, 8)>>>(whh, HH, 1);
    gx_kernel<<<dim3(16, 50), 256>>>(input);

    loop_kernel<<<NBLK, 256, loop_smem>>>(c0, out_outputs, out_cx);

    scan_kernel<<<BB * H3 / 256, 256>>>(out_evb);
    ev_mma_kernel<<<dim3(II / 128, H3 / 128, BB), 256>>>(input, II, out_evih);
    ev_mma_kernel<<<dim3(HH / 128, H3 / 128, BB), 256>>>(nullptr, HH, out_evhh);
}

// round 17
// speedup vs baseline: 1.6546x; 1.0610x over previous
#include <cuda_runtime.h>
#include <math.h>

#define TT 100
#define BB 64
#define II 256
#define HH 512
#define H3 1536
#define H4 2048
#define NBLK 128          // persistent grid size (all co-resident)
#define KC 8              // K split chunks (512/64)
#define BKC 64            // K per chunk
#define AROW 40           // Asm row stride: fragment reads bank = 8cg+gr (conflict-free)
#define WROW 68           // Whi/Wlo row stride: b-reads bank = 4gr+cg (conflict-free)

#define PF4(x) ((x) + ((x) >> 3))

// producer: release-add (no separate fence needed)
__device__ __forceinline__ void sig_add(unsigned* p) {
    asm volatile("red.release.gpu.global.add.u32 [%0], 1;" :: "l"(p) : "memory");
}

// ---------------- tf32 mma helpers (layouts validated R15/R16) ----------------
__device__ __forceinline__ unsigned f2tf32(float v) {
    unsigned r;
    asm("cvt.rna.tf32.f32 %0, %1;" : "=r"(r) : "f"(v));
    return r;
}
__device__ __forceinline__ void mma_tf32(float* d, const unsigned* a, unsigned b0, unsigned b1) {
    asm volatile("mma.sync.aligned.m16n8k8.row.col.f32.tf32.tf32.f32 "
                 "{%0,%1,%2,%3}, {%4,%5,%6,%7}, {%8,%9}, {%0,%1,%2,%3};"
                 : "+f"(d[0]), "+f"(d[1]), "+f"(d[2]), "+f"(d[3])
                 : "r"(a[0]), "r"(a[1]), "r"(a[2]), "r"(a[3]), "r"(b0), "r"(b1));
}

// ---------------- scratch (device globals) ----------------
__device__ float g_WihP[II * H4];                 // packed: [k][ (n%512)*4 + n/512 ]
__device__ float g_WhhP[HH * H4];
__device__ float g_biasP[H4];
__device__ float g_Gx[(size_t)TT * BB * H4];      // packed gate pre-activations from input path
__device__ float g_h[(size_t)(TT + 1) * BB * HH]; // h history [t][b][h]
__device__ float g_f[(size_t)TT * BB * HH];
__device__ float g_d[(size_t)TT * BB * H3];       // later overwritten with w = d * suffix-prod(f)
__device__ float g_gpart[16 * 32 * H4];           // split-K partials [kcmh][m-local][packed n]
__device__ unsigned g_cnt_g[TT][8];               // partials-done counters per (t, nt)
__device__ unsigned g_cnt_c[TT][8];               // cells-done counters per (t, nt)

// ---------------- prep ----------------
__global__ void prep_kernel(const float* __restrict__ h0, const float* __restrict__ bih,
                            const float* __restrict__ bhh) {
    int i = blockIdx.x * blockDim.x + threadIdx.x;
    if (i < TT * 8) { (&g_cnt_g[0][0])[i] = 0u; (&g_cnt_c[0][0])[i] = 0u; }
    if (i < H4) g_biasP[(i & 511) * 4 + (i >> 9)] = bih[i] + bhh[i];
    if (i < BB * HH) g_h[i] = h0[i];
}

// ---------------- pack weights: in[2048][K] -> out[K][2048 packed] ----------------
__global__ void pack_w(const float* __restrict__ in, int K, int which) {
    __shared__ float s[32][33];
    int k0 = blockIdx.x * 32, n0 = blockIdx.y * 32;
    int tx = threadIdx.x, ty = threadIdx.y;
    for (int i = ty; i < 32; i += 8)
        s[i][tx] = in[(size_t)(n0 + i) * K + k0 + tx];
    __syncthreads();
    float* out = which ? g_WhhP : g_WihP;
    int g = n0 >> 9;
    int c = n0 & 511;
    for (int i = ty; i < 32; i += 8)
        out[(size_t)(k0 + i) * H4 + (c + tx) * 4 + g] = s[tx][i];
}

// ---------------- Gx = X[6400,256] @ WihP + biasP via tf32 hi/lo mma ----------------
// Block tile 128m x 128n, K=256 in 8-chunks. 8 warps = 4 m-groups(32) x 2 n-groups(64).
// hi/lo computed ONCE at staging; fragments are plain conflict-free LDS (row pad 136).
__global__ void __launch_bounds__(256, 2) gx_kernel(const float* __restrict__ X) {
    __shared__ float Ahi[8][136], Alo[8][136];   // [k][m]
    __shared__ float Bhi[8][136], Blo[8][136];   // [k][n]
    const int tid = threadIdx.x;
    const int n0 = blockIdx.x * 128;
    const int m0 = blockIdx.y * 128;
    const int w = tid >> 5, lane = tid & 31;
    const int gr = lane >> 2, cg = lane & 3;
    const int jbase = (w & 3) * 32;              // m-slice
    const int kbase = (w >> 2) * 64;             // n-slice
    const int am = tid >> 1, ak = (tid & 1) * 4; // X staging: 128 m x 2 k-quads
    const int bk = tid >> 5, bn = (tid & 31) * 4;// W staging

    float acc[2][8][4];
#pragma unroll
    for (int mi = 0; mi < 2; mi++)
#pragma unroll
        for (int ni = 0; ni < 8; ni++)
#pragma unroll
            for (int q = 0; q < 4; q++) acc[mi][ni][q] = 0.f;

    for (int k0 = 0; k0 < II; k0 += 8) {
        float4 xv = *(const float4*)(X + (size_t)(m0 + am) * II + k0 + ak);
        float4 wv = *(const float4*)(g_WihP + (size_t)(k0 + bk) * H4 + n0 + bn);
        // X hi/lo, transposed store [k][m]
        float xq[4] = {xv.x, xv.y, xv.z, xv.w};
#pragma unroll
        for (int q = 0; q < 4; q++) {
            float hf = __uint_as_float(f2tf32(xq[q]));
            Ahi[ak + q][am] = hf;
            Alo[ak + q][am] = __uint_as_float(f2tf32(xq[q] - hf));
        }
        // W hi/lo, [k][n]
        float4 h4, l4;
        h4.x = __uint_as_float(f2tf32(wv.x)); l4.x = __uint_as_float(f2tf32(wv.x - h4.x));
        h4.y = __uint_as_float(f2tf32(wv.y)); l4.y = __uint_as_float(f2tf32(wv.y - h4.y));
        h4.z = __uint_as_float(f2tf32(wv.z)); l4.z = __uint_as_float(f2tf32(wv.z - h4.z));
        h4.w = __uint_as_float(f2tf32(wv.w)); l4.w = __uint_as_float(f2tf32(wv.w - h4.w));
        *(float4*)&Bhi[bk][bn] = h4;
        *(float4*)&Blo[bk][bn] = l4;
        __syncthreads();

        unsigned ahi[2][4], alo[2][4];
#pragma unroll
        for (int mi = 0; mi < 2; mi++) {
            int jr = jbase + mi * 16 + gr;
            ahi[mi][0] = __float_as_uint(Ahi[cg][jr]);
            ahi[mi][1] = __float_as_uint(Ahi[cg][jr + 8]);
            ahi[mi][2] = __float_as_uint(Ahi[cg + 4][jr]);
            ahi[mi][3] = __float_as_uint(Ahi[cg + 4][jr + 8]);
            alo[mi][0] = __float_as_uint(Alo[cg][jr]);
            alo[mi][1] = __float_as_uint(Alo[cg][jr + 8]);
            alo[mi][2] = __float_as_uint(Alo[cg + 4][jr]);
            alo[mi][3] = __float_as_uint(Alo[cg + 4][jr + 8]);
        }
#pragma unroll
        for (int ni = 0; ni < 8; ni++) {
            int kc = kbase + ni * 8 + gr;
            unsigned bhi0 = __float_as_uint(Bhi[cg][kc]);
            unsigned bhi1 = __float_as_uint(Bhi[cg + 4][kc]);
            unsigned blo0 = __float_as_uint(Blo[cg][kc]);
            unsigned blo1 = __float_as_uint(Blo[cg + 4][kc]);
#pragma unroll
            for (int mi = 0; mi < 2; mi++) {
                mma_tf32(acc[mi][ni], ahi[mi], bhi0, bhi1);
                mma_tf32(acc[mi][ni], ahi[mi], blo0, blo1);
                mma_tf32(acc[mi][ni], alo[mi], bhi0, bhi1);
            }
        }
        __syncthreads();
    }

    // store + bias: d0=D[gr][2cg], d1=D[gr][2cg+1], d2=D[gr+8][2cg], d3=D[gr+8][2cg+1]
#pragma unroll
    for (int mi = 0; mi < 2; mi++) {
        int mrow = m0 + jbase + mi * 16 + gr;
#pragma unroll
        for (int ni = 0; ni < 8; ni++) {
            int col = n0 + kbase + ni * 8 + 2 * cg;
            float2 bi = *(const float2*)(g_biasP + col);
            *(float2*)(g_Gx + (size_t)mrow * H4 + col) =
                make_float2(acc[mi][ni][0] + bi.x, acc[mi][ni][1] + bi.y);
            *(float2*)(g_Gx + (size_t)(mrow + 8) * H4 + col) =
                make_float2(acc[mi][ni][2] + bi.x, acc[mi][ni][3] + bi.y);
        }
    }
}

// ---------------- persistent recurrent loop: R16 proven (tf32 hi/lo mma, split-K) ----------------
__global__ void __launch_bounds__(256, 1)
loop_kernel(const float* __restrict__ c0, float* __restrict__ out_h, float* __restrict__ out_c) {
    extern __shared__ float sm[];
    float* Whi = sm;                    // [256 n][WROW]  (~69.6 KB)
    float* Wlo = sm + 256 * WROW;       // [256 n][WROW]  (~69.6 KB)
    float* Asm = Wlo + 256 * WROW;      // [64 k][AROW]   (10.2 KB)

    const int tid = threadIdx.x;
    const int nt = blockIdx.x & 7;
    const int kcmh = blockIdx.x >> 3;    // 0..15
    const int kc = kcmh >> 1;            // 0..7
    const int mh = kcmh & 1;             // 0..1
    const int n0 = nt * 256;
    const int k0 = kc * BKC;
    const int m0 = mh * 32;

    // ---- stage hi/lo weights once: [n local][k local] ----
    {
        const float* wsrc = g_WhhP + (size_t)k0 * H4 + n0;
#pragma unroll
        for (int r = 0; r < 16; r++) {
            int e = r * 256 + tid;
            int kk = e >> 6;            // k local 0..63
            int nf4 = e & 63;           // n f4 0..63
            float4 wv = *(const float4*)(wsrc + (size_t)kk * H4 + nf4 * 4);
            float wq[4] = {wv.x, wv.y, wv.z, wv.w};
#pragma unroll
            for (int q = 0; q < 4; q++) {
                float hf = __uint_as_float(f2tf32(wq[q]));
                float lf = __uint_as_float(f2tf32(wq[q] - hf));
                Whi[(size_t)(nf4 * 4 + q) * WROW + kk] = hf;
                Wlo[(size_t)(nf4 * 4 + q) * WROW + kk] = lf;
            }
        }
    }

    const int w = tid >> 5, lane = tid & 31;
    const int gr = lane >> 2;            // 0..7
    const int cg = lane & 3;             // 0..3
    const int nb = w * 32;               // warp n-slice within 256
    const int am = tid >> 3, ak = (tid & 7) * 8;   // A staging map (R12-proven)

    // cell identity (fixed all steps)
    const int cb = kcmh * 4 + (tid >> 6);    // batch
    const int ch = nt * 64 + (tid & 63);     // global h col
    float creg = c0[(size_t)cb * HH + ch];

    for (int t = 0; t < TT; t++) {
        // ---- wait for h[t] producers (skip t=0: prep wrote it). nt_src = kc. ----
        if (t > 0) {
            if (tid == 0) {
                volatile unsigned* p = &g_cnt_c[t - 1][kc];
                while (*p < 16u) __nanosleep(64);
                __threadfence();
            }
            __syncthreads();
        }

        // ---- stage A: h[t][m0..m0+32)[k0..k0+64) -> Asm[k][m] ----
        const float* hsrc = g_h + (size_t)t * BB * HH;
        float4 v0 = __ldcg((const float4*)(hsrc + (size_t)(m0 + am) * HH + k0 + ak));
        float4 v1 = __ldcg((const float4*)(hsrc + (size_t)(m0 + am) * HH + k0 + ak + 4));
        Asm[(ak + 0) * AROW + am] = v0.x; Asm[(ak + 1) * AROW + am] = v0.y;
        Asm[(ak + 2) * AROW + am] = v0.z; Asm[(ak + 3) * AROW + am] = v0.w;
        Asm[(ak + 4) * AROW + am] = v1.x; Asm[(ak + 5) * AROW + am] = v1.y;
        Asm[(ak + 6) * AROW + am] = v1.z; Asm[(ak + 7) * AROW + am] = v1.w;

        // prefetch this step's Gx for the cell (independent of GEMM)
        float4 gx4 = __ldcg((const float4*)(g_Gx + ((size_t)t * BB + cb) * H4 + 4 * ch));
        __syncthreads();

        // ---- GEMM 32x256, K=64 via tf32 mma hi/lo ----
        float acc[2][4][4];
#pragma unroll
        for (int mi = 0; mi < 2; mi++)
#pragma unroll
            for (int ni = 0; ni < 4; ni++)
#pragma unroll
                for (int q = 0; q < 4; q++) acc[mi][ni][q] = 0.f;

#pragma unroll
        for (int ks = 0; ks < 8; ks++) {
            unsigned ahi[2][4], alo[2][4];
#pragma unroll
            for (int mi = 0; mi < 2; mi++) {
                int mb = mi * 16 + gr;
                float e0 = Asm[(ks * 8 + cg) * AROW + mb];
                float e1 = Asm[(ks * 8 + cg) * AROW + mb + 8];
                float e2 = Asm[(ks * 8 + cg + 4) * AROW + mb];
                float e3 = Asm[(ks * 8 + cg + 4) * AROW + mb + 8];
                ahi[mi][0] = f2tf32(e0); alo[mi][0] = f2tf32(e0 - __uint_as_float(ahi[mi][0]));
                ahi[mi][1] = f2tf32(e1); alo[mi][1] = f2tf32(e1 - __uint_as_float(ahi[mi][1]));
                ahi[mi][2] = f2tf32(e2); alo[mi][2] = f2tf32(e2 - __uint_as_float(ahi[mi][2]));
                ahi[mi][3] = f2tf32(e3); alo[mi][3] = f2tf32(e3 - __uint_as_float(ahi[mi][3]));
            }
#pragma unroll
            for (int ni = 0; ni < 4; ni++) {
                int n = nb + ni * 8 + gr;
                unsigned bhi0 = __float_as_uint(Whi[(size_t)n * WROW + ks * 8 + cg]);
                unsigned bhi1 = __float_as_uint(Whi[(size_t)n * WROW + ks * 8 + cg + 4]);
                unsigned blo0 = __float_as_uint(Wlo[(size_t)n * WROW + ks * 8 + cg]);
                unsigned blo1 = __float_as_uint(Wlo[(size_t)n * WROW + ks * 8 + cg + 4]);
#pragma unroll
                for (int mi = 0; mi < 2; mi++) {
                    mma_tf32(acc[mi][ni], ahi[mi], bhi0, bhi1);
                    mma_tf32(acc[mi][ni], ahi[mi], blo0, blo1);
                    mma_tf32(acc[mi][ni], alo[mi], bhi0, bhi1);
                }
            }
        }

        // ---- write partials: D[m][n] rows gr / gr+8 per mtile ----
#pragma unroll
        for (int mi = 0; mi < 2; mi++) {
            int mrow = mi * 16 + gr;
#pragma unroll
            for (int ni = 0; ni < 4; ni++) {
                int col = n0 + nb + ni * 8 + 2 * cg;
                float* p0 = g_gpart + ((size_t)kcmh * 32 + mrow) * H4 + col;
                float* p1 = g_gpart + ((size_t)kcmh * 32 + mrow + 8) * H4 + col;
                *(float2*)p0 = make_float2(acc[mi][ni][0], acc[mi][ni][1]);
                *(float2*)p1 = make_float2(acc[mi][ni][2], acc[mi][ni][3]);
            }
        }

        // ---- signal partials done (release-add), wait for all 16 producers of our nt ----
        __syncthreads();                      // Asm also reused next step
        if (tid == 0) {
            sig_add(&g_cnt_g[t][nt]);
            volatile unsigned* p = &g_cnt_g[t][nt];
            while (*p < 16u) __nanosleep(64);
            __threadfence();
        }
        __syncthreads();

        // ---- cell for (cb, ch): sum 8 partials (kc 0..7, mh = cb>>5) ----
        {
            float4 g4 = gx4;
#pragma unroll
            for (int q = 0; q < KC; q++) {
                int pk = q * 2 + (cb >> 5);
                float4 p = __ldcg((const float4*)(g_gpart + ((size_t)pk * 32 + (cb & 31)) * H4 + 4 * ch));
                g4.x += p.x; g4.y += p.y; g4.z += p.z; g4.w += p.w;
            }
            float i = 1.f / (1.f + expf(-g4.x));
            float f = 1.f / (1.f + expf(-g4.y));
            float g = tanhf(g4.z);
            float o = 1.f / (1.f + expf(-g4.w));
            float cx = creg;
            float cy = f * cx + i * g;
            float hy = o * tanhf(cy);
            creg = cy;
            size_t hb = (size_t)cb * HH + ch;
            g_h[(size_t)(t + 1) * BB * HH + hb] = hy;
            out_h[(size_t)t * BB * HH + hb] = hy;
            g_f[(size_t)t * BB * HH + hb] = f;
            size_t db = (size_t)t * BB * H3 + (size_t)cb * H3 + ch;
            g_d[db]          = g * i * (1.f - i);
            g_d[db + HH]     = cx * f * (1.f - f);
            g_d[db + 2 * HH] = i * (1.f - g) * (1.f + g);
            if (t == TT - 1) out_c[hb] = cy;
        }

        // ---- signal cells done (release-add) ----
        __syncthreads();
        if (tid == 0) sig_add(&g_cnt_c[t][nt]);
    }
}

// ---------------- reverse suffix-product scan ----------------
__global__ void scan_kernel(float* __restrict__ evb_out) {
    int idx = blockIdx.x * blockDim.x + threadIdx.x;  // < BB*H3
    int b = idx / H3, j = idx % H3;
    int h = j & (HH - 1);
    float p = 1.f, sum = 0.f;
    for (int t = TT - 1; t >= 0; t--) {
        size_t di = (size_t)t * BB * H3 + (size_t)b * H3 + j;
        float w = g_d[di] * p;
        g_d[di] = w;
        sum += w;
        p *= g_f[(size_t)t * BB * HH + (size_t)b * HH + h];
    }
    evb_out[idx] = sum;
}

// ---------------- batched ev GEMM via tf32 mma, double-buffered smem staging ----------------
// Block tile: 128 j x 128 k per batch; 8 warps = 4 j-groups(32) x 2 k-groups(64).
// One __syncthreads per k-slice; LDG prefetch overlaps the mma phase.
__global__ void __launch_bounds__(256, 2)
ev_mma_kernel(const float* __restrict__ Xs, int kdim, float* __restrict__ out) {
    __shared__ float Ws[2][8][136];
    __shared__ float Xm[2][8][136];
    if (Xs == nullptr) Xs = g_h;  // ev_hh: h_{t-1} history = g_h[t] slice
    const int tid = threadIdx.x;
    const int b = blockIdx.z;
    const int j0 = blockIdx.y * 128;
    const int k0 = blockIdx.x * 128;
    const int w = tid >> 5, lane = tid & 31;
    const int gr = lane >> 2;            // 0..7
    const int cg = lane & 3;             // 0..3
    const int jbase = (w & 3) * 32;
    const int kbase = (w >> 2) * 64;
    const int lc = lane;                 // staging f4 col

    float acc[2][8][4];
#pragma unroll
    for (int mi = 0; mi < 2; mi++)
#pragma unroll
        for (int ni = 0; ni < 8; ni++)
#pragma unroll
            for (int q = 0; q < 4; q++) acc[mi][ni][q] = 0.f;

    // prologue: stage slice 0 into buf 0 (t = w, always < 100)
    {
        float4 wv = *(const float4*)(g_d + (size_t)w * BB * H3 + (size_t)b * H3 + j0 + lc * 4);
        float4 xv = *(const float4*)(Xs + ((size_t)w * BB + b) * kdim + k0 + lc * 4);
        *(float4*)&Ws[0][w][lc * 4] = wv;
        *(float4*)&Xm[0][w][lc * 4] = xv;
    }
    __syncthreads();

    for (int ks = 0; ks < 13; ks++) {
        const int cur = ks & 1;
        // prefetch next slice (overlaps mma below)
        float4 wv = make_float4(0.f, 0.f, 0.f, 0.f);
        float4 xv = make_float4(0.f, 0.f, 0.f, 0.f);
        if (ks < 12) {
            int t = (ks + 1) * 8 + w;
            if (t < TT) {
                wv = *(const float4*)(g_d + (size_t)t * BB * H3 + (size_t)b * H3 + j0 + lc * 4);
                xv = *(const float4*)(Xs + ((size_t)t * BB + b) * kdim + k0 + lc * 4);
            }
        }

        unsigned afr[2][4];
#pragma unroll
        for (int mi = 0; mi < 2; mi++) {
            int jr = jbase + mi * 16 + gr;
            afr[mi][0] = f2tf32(Ws[cur][cg][jr]);
            afr[mi][1] = f2tf32(Ws[cur][cg][jr + 8]);
            afr[mi][2] = f2tf32(Ws[cur][cg + 4][jr]);
            afr[mi][3] = f2tf32(Ws[cur][cg + 4][jr + 8]);
        }
#pragma unroll
        for (int ni = 0; ni < 8; ni++) {
            int kc = kbase + ni * 8 + gr;
            unsigned b0 = f2tf32(Xm[cur][cg][kc]);
            unsigned b1 = f2tf32(Xm[cur][cg + 4][kc]);
            mma_tf32(acc[0][ni], afr[0], b0, b1);
            mma_tf32(acc[1][ni], afr[1], b0, b1);
        }

        if (ks < 12) {
            *(float4*)&Ws[cur ^ 1][w][lc * 4] = wv;
            *(float4*)&Xm[cur ^ 1][w][lc * 4] = xv;
        }
        __syncthreads();
    }

    // store: d0=D[gr][2c], d1=D[gr][2c+1], d2=D[gr+8][2c], d3=D[gr+8][2c+1]
#pragma unroll
    for (int mi = 0; mi < 2; mi++) {
        int jr = j0 + jbase + mi * 16 + gr;
#pragma unroll
        for (int ni = 0; ni < 8; ni++) {
            int col = k0 + kbase + ni * 8 + 2 * cg;
            float* o0 = out + ((size_t)b * H3 + jr) * kdim + col;
            float* o1 = out + ((size_t)b * H3 + jr + 8) * kdim + col;
            *(float2*)o0 = make_float2(acc[mi][ni][0], acc[mi][ni][1]);
            *(float2*)o1 = make_float2(acc[mi][ni][2], acc[mi][ni][3]);
        }
    }
}

// ---------------- launch ----------------
extern "C" void kernel_launch(void* const* d_in, const int* in_sizes, int n_in,
                              void* d_out, int out_size) {
    (void)in_sizes; (void)n_in; (void)out_size;
    const float* input = (const float*)d_in[0];
    const float* h0    = (const float*)d_in[1];
    const float* c0    = (const float*)d_in[2];
    const float* wih   = (const float*)d_in[3];
    const float* whh   = (const float*)d_in[4];
    const float* bih   = (const float*)d_in[5];
    const float* bhh   = (const float*)d_in[6];

    float* out         = (float*)d_out;
    float* out_outputs = out;
    float* out_cx      = out_outputs + (size_t)TT * BB * HH;
    float* out_evih    = out_cx + (size_t)BB * HH;
    float* out_evhh    = out_evih + (size_t)BB * H3 * II;
    float* out_evb     = out_evhh + (size_t)BB * H3 * HH;

    const int loop_smem = (2 * 256 * WROW + 64 * AROW) * 4;   // ~146 KB
    cudaFuncSetAttribute(loop_kernel, cudaFuncAttributeMaxDynamicSharedMemorySize, loop_smem);

    prep_kernel<<<512, 256>>>(h0, bih, bhh);
    pack_w<<<dim3(II / 32, H4 / 32), dim3(32, 8)>>>(wih, II, 0);
    pack_w<<<dim3(HH / 32, H4 / 32), dim3(32, 8)>>>(whh, HH, 1);
    gx_kernel<<<dim3(16, 50), 256>>>(input);

    loop_kernel<<<NBLK, 256, loop_smem>>>(c0, out_outputs, out_cx);

    scan_kernel<<<BB * H3 / 256, 256>>>(out_evb);
    ev_mma_kernel<<<dim3(II / 128, H3 / 128, BB), 256>>>(input, II, out_evih);
    ev_mma_kernel<<<dim3(HH / 128, H3 / 128, BB), 256>>>(nullptr, HH, out_evhh);
}